// round 16
// baseline (speedup 1.0000x reference)
#include <cuda_runtime.h>
#include <cuda_fp16.h>
#include <cuda_bf16.h>
#include <cstdint>

#define N_EDGES 800000
#define N_NODES 50000
#define MID 3
#define NVEC 32
#define ROW (MID * NVEC)            // 96 halves = 192 B per node row
#define ROWS_TOTAL (N_NODES * MID)  // 150000 A-rows of 32 halves (64 B)
#define GROUP_ROWS 48               // rows per block (3 MMA row-tiles)
#define NGROUPS (ROWS_TOTAL / GROUP_ROWS)   // 3125 exactly
#define SMEM_ROW_B 80               // 64 B data + 16 B pad (conflict-free ldmatrix)

// Per-node fp16 accumulators, zero at entry of every kernel_launch
// (zero-init at module load; mix kernel restores zeros after consuming).
__device__ __half g_xn1[N_NODES * ROW];
__device__ __half g_xn2[N_NODES * ROW];

__device__ __forceinline__ unsigned pack_h2(float a, float b) {
    __half2 h = __floats2half2_rn(a, b);
    return *reinterpret_cast<unsigned*>(&h);
}
__device__ __forceinline__ unsigned pack_hh(__half a, __half b) {
    return ((unsigned)__half_as_ushort(b) << 16) | (unsigned)__half_as_ushort(a);
}

__device__ __forceinline__ void red_add_v4_f16x2(void* addr,
                                                 unsigned h0, unsigned h1,
                                                 unsigned h2, unsigned h3) {
    asm volatile("red.global.add.noftz.v4.f16x2 [%0], {%1, %2, %3, %4};"
                 :: "l"(addr), "r"(h0), "r"(h1), "r"(h2), "r"(h3)
                 : "memory");
}

__device__ __forceinline__ float4 ldcs_f4(const float4* p) { return __ldcs(p); }

__device__ __forceinline__ unsigned smem_u32(const void* p) {
    return (unsigned)__cvta_generic_to_shared(p);
}
__device__ __forceinline__ void cpasync16(unsigned saddr, const void* g) {
    asm volatile("cp.async.cg.shared.global [%0], [%1], 16;"
                 :: "r"(saddr), "l"(g) : "memory");
}
__device__ __forceinline__ void ldsm4(unsigned* a, unsigned saddr) {
    asm volatile("ldmatrix.sync.aligned.m8n8.x4.shared.b16 {%0,%1,%2,%3}, [%4];"
                 : "=r"(a[0]), "=r"(a[1]), "=r"(a[2]), "=r"(a[3])
                 : "r"(saddr));
}
__device__ __forceinline__ void mma16816(float* c, const unsigned* a, const unsigned* b) {
    asm volatile("mma.sync.aligned.m16n8k16.row.col.f32.f16.f16.f32 "
                 "{%0,%1,%2,%3}, {%4,%5,%6,%7}, {%8,%9}, {%0,%1,%2,%3};"
                 : "+f"(c[0]), "+f"(c[1]), "+f"(c[2]), "+f"(c[3])
                 : "r"(a[0]), "r"(a[1]), "r"(a[2]), "r"(a[3]),
                   "r"(b[0]), "r"(b[1]));
}

// ---------------------------------------------------------------------------
// Kernel 1: edge scatter — EXACT R13 form (measured 80.7us; hand-reordered
// load batching regressed it, so ptxas's interleaved schedule stays).
// 4 threads/edge, fp16 RED.128.
// ---------------------------------------------------------------------------
__global__ void __launch_bounds__(256)
edge_scatter_kernel(const float4* __restrict__ xe4,   // [E*3*8]
                    const float4* __restrict__ W4,    // [E*8]
                    const int*    __restrict__ src,
                    const int*    __restrict__ dst) {
    int gid = blockIdx.x * blockDim.x + threadIdx.x;
    int e   = gid >> 2;
    int sub = gid & 3;
    if (e >= N_EDGES) return;

    const float4* Wp = W4 + e * 8 + sub * 2;
    float4 w0 = ldcs_f4(&Wp[0]);
    float4 w1 = ldcs_f4(&Wp[1]);

    int d = __ldcs(&dst[e]);
    int s = __ldcs(&src[e]);

    char* p1 = reinterpret_cast<char*>(g_xn1) + (size_t)d * (ROW * 2) + sub * 16;
    char* p2 = reinterpret_cast<char*>(g_xn2) + (size_t)s * (ROW * 2) + sub * 16;

#pragma unroll
    for (int m = 0; m < MID; m++) {
        const float4* xp = xe4 + (e * MID + m) * 8 + sub * 2;
        float4 x0 = ldcs_f4(&xp[0]);
        float4 x1 = ldcs_f4(&xp[1]);

        unsigned h0 = pack_h2(w0.x * x0.x, w0.y * x0.y);
        unsigned h1 = pack_h2(w0.z * x0.z, w0.w * x0.w);
        unsigned h2 = pack_h2(w1.x * x1.x, w1.y * x1.y);
        unsigned h3 = pack_h2(w1.z * x1.z, w1.w * x1.w);

        red_add_v4_f16x2(p1 + m * (NVEC * 2), h0, h1, h2, h3);
        red_add_v4_f16x2(p2 + m * (NVEC * 2), h0, h1, h2, h3);
    }
}

// ---------------------------------------------------------------------------
// Kernel 2: tensor-core mix + zero-restore — one 48-row group per block.
// Per block: ONE cp.async batch (6KB, both arrays), ONE wait+barrier, then
// each warp does 3 row-tiles x 8 HMMA for its 8-col slice, st.v2.f32 out,
// zero-restore.  No intra-block loop -> per-tile barrier cost amortized 6x;
// inter-block parallelism (16 blocks/SM) hides the load latency.
// ---------------------------------------------------------------------------
__global__ void __launch_bounds__(128)
node_mix_mma_kernel(const float* __restrict__ M1,
                    const float* __restrict__ M2,
                    float* __restrict__ out) {
    __shared__ __align__(128) char sbuf[2][GROUP_ROWS * SMEM_ROW_B];

    const int tid  = threadIdx.x;
    const int warp = tid >> 5;
    const int lane = tid & 31;
    const int q = lane & 3;
    const int g = lane >> 2;
    const int n0 = warp * 8;
    const int r0 = blockIdx.x * GROUP_ROWS;

    // ---- issue the group's loads first (12 cp.async per thread-triple) ----
    // 768 chunks of 16B total: arr = c/192, row = (c%192)>>2, chunk = c&3
#pragma unroll
    for (int i = 0; i < 3; i++) {
        int c     = tid + 128 * i;
        int arr   = c >= 192;
        int rem   = arr ? c - 192 : c;
        int row   = rem >> 2;
        int chunk = rem & 3;
        const char* gsrc = arr ? (const char*)g_xn2 : (const char*)g_xn1;
        unsigned d = smem_u32(&sbuf[arr][row * SMEM_ROW_B + chunk * 16]);
        cpasync16(d, gsrc + (size_t)(r0 + row) * 64 + chunk * 16);
    }
    asm volatile("cp.async.commit_group;" ::: "memory");

    // ---- build B fragments while loads are in flight ----
    unsigned bh[2][2][2], bl[2][2][2];
#pragma unroll
    for (int ks = 0; ks < 2; ks++) {
#pragma unroll
        for (int r = 0; r < 2; r++) {
            int k = ks * 16 + q * 2 + r * 8;
            int n = n0 + g;
            float m1a = M1[k * 32 + n],       m2a = M2[k * 32 + n];
            float m1b = M1[(k + 1) * 32 + n], m2b = M2[(k + 1) * 32 + n];
            float maa = 0.5f * (m1a + m2a), mab = 0.5f * (m1b + m2b);
            float mba = 0.5f * (m2a - m1a), mbb = 0.5f * (m2b - m1b);

            __half ha = __float2half_rn(maa), hb = __float2half_rn(mab);
            bh[0][ks][r] = pack_hh(ha, hb);
            bl[0][ks][r] = pack_hh(__float2half_rn(maa - __half2float(ha)),
                                   __float2half_rn(mab - __half2float(hb)));
            ha = __float2half_rn(mba); hb = __float2half_rn(mbb);
            bh[1][ks][r] = pack_hh(ha, hb);
            bl[1][ks][r] = pack_hh(__float2half_rn(mba - __half2float(ha)),
                                   __float2half_rn(mbb - __half2float(hb)));
        }
    }

    asm volatile("cp.async.wait_group 0;" ::: "memory");
    __syncthreads();

    // ---- 3 row-tiles of 16, each: ldmatrix A (both arrays) + 8 HMMA ----
#pragma unroll
    for (int t = 0; t < 3; t++) {
        unsigned a1[2][4], a2[2][4];
        unsigned off = (t * 16 + (lane & 15)) * SMEM_ROW_B + (lane >> 4) * 16;
        unsigned base1 = smem_u32(&sbuf[0][0]) + off;
        unsigned base2 = smem_u32(&sbuf[1][0]) + off;
        ldsm4(a1[0], base1);  ldsm4(a1[1], base1 + 32);
        ldsm4(a2[0], base2);  ldsm4(a2[1], base2 + 32);

        float c[4] = {0.f, 0.f, 0.f, 0.f};
#pragma unroll
        for (int ks = 0; ks < 2; ks++) {
            mma16816(c, a1[ks], bh[0][ks]);
            mma16816(c, a1[ks], bl[0][ks]);
            mma16816(c, a2[ks], bh[1][ks]);
            mma16816(c, a2[ks], bl[1][ks]);
        }

        int rr = r0 + t * 16 + g;
        *reinterpret_cast<float2*>(out + (size_t)rr * 32 + n0 + q * 2)       = make_float2(c[0], c[1]);
        *reinterpret_cast<float2*>(out + (size_t)(rr + 8) * 32 + n0 + q * 2) = make_float2(c[2], c[3]);
    }

    // ---- zero-restore the group's accumulator bytes (reads are complete:
    //      all data came through smem before the barrier above) ----
    const uint4 z = make_uint4(0u, 0u, 0u, 0u);
#pragma unroll
    for (int i = 0; i < 3; i++) {
        int c     = tid + 128 * i;
        int arr   = c >= 192;
        int rem   = arr ? c - 192 : c;
        int row   = rem >> 2;
        int chunk = rem & 3;
        char* gdst = arr ? (char*)g_xn2 : (char*)g_xn1;
        *reinterpret_cast<uint4*>(gdst + (size_t)(r0 + row) * 64 + chunk * 16) = z;
    }
}

// ---------------------------------------------------------------------------
// Launch.  Inputs (metadata order): xe, W, M1, M2, xe_src, xe_dst, n_nodes
// ---------------------------------------------------------------------------
extern "C" void kernel_launch(void* const* d_in, const int* in_sizes, int n_in,
                              void* d_out, int out_size) {
    const float4* xe4 = (const float4*)d_in[0];
    const float4* W4  = (const float4*)d_in[1];
    const float*  M1  = (const float*)d_in[2];
    const float*  M2  = (const float*)d_in[3];
    const int*    src = (const int*)d_in[4];
    const int*    dst = (const int*)d_in[5];
    float* out = (float*)d_out;

    // 1) edge scatter (4 threads per edge, R13 schedule)
    {
        long long nthreads = (long long)N_EDGES * 4;
        int blocks = (int)((nthreads + 255) / 256);
        edge_scatter_kernel<<<blocks, 256>>>(xe4, W4, src, dst);
    }
    // 2) tensor-core mix + zero-restore (one 48-row group per block)
    node_mix_mma_kernel<<<NGROUPS, 128>>>(M1, M2, out);
}

// round 17
// speedup vs baseline: 1.0112x; 1.0112x over previous
#include <cuda_runtime.h>
#include <cuda_fp16.h>
#include <cuda_bf16.h>
#include <cstdint>

#define N_EDGES 800000
#define N_NODES 50000
#define MID 3
#define NVEC 32
#define ROW (MID * NVEC)            // 96 halves = 192 B per node row
#define ROWS_TOTAL (N_NODES * MID)  // 150000 A-rows of 32 halves (64 B)
#define RTILES (ROWS_TOTAL / 16)    // 9375 row-tiles of 16 rows
#define MIX_BLOCKS 1184             // best measured mix config (R13: 12.7us)
#define SMEM_ROW_B 80               // 64 B data + 16 B pad (conflict-free ldmatrix)
#define EDGE_BLOCKS ((N_EDGES * 4 + 255) / 256)   // 12500

// Per-node fp16 accumulators, zero at entry of every kernel_launch
// (zero-init at module load; mix kernel restores zeros after consuming).
__device__ __half g_xn1[N_NODES * ROW];
__device__ __half g_xn2[N_NODES * ROW];

// Precomputed HMMA B fragments: per tid (0..127), 8 hi words then 8 lo words.
// Index within the 8: mat*4 + ks*2 + r.  Built by the extra edge-grid block.
__device__ __align__(16) unsigned g_bfrag[128 * 16];

__device__ __forceinline__ unsigned pack_h2(float a, float b) {
    __half2 h = __floats2half2_rn(a, b);
    return *reinterpret_cast<unsigned*>(&h);
}
__device__ __forceinline__ unsigned pack_hh(__half a, __half b) {
    return ((unsigned)__half_as_ushort(b) << 16) | (unsigned)__half_as_ushort(a);
}

__device__ __forceinline__ void red_add_v4_f16x2(void* addr,
                                                 unsigned h0, unsigned h1,
                                                 unsigned h2, unsigned h3) {
    asm volatile("red.global.add.noftz.v4.f16x2 [%0], {%1, %2, %3, %4};"
                 :: "l"(addr), "r"(h0), "r"(h1), "r"(h2), "r"(h3)
                 : "memory");
}

__device__ __forceinline__ float4 ldcs_f4(const float4* p) { return __ldcs(p); }

__device__ __forceinline__ unsigned smem_u32(const void* p) {
    return (unsigned)__cvta_generic_to_shared(p);
}
__device__ __forceinline__ void cpasync16(unsigned saddr, const void* g) {
    asm volatile("cp.async.cg.shared.global [%0], [%1], 16;"
                 :: "r"(saddr), "l"(g) : "memory");
}
__device__ __forceinline__ void ldsm4(unsigned* a, unsigned saddr) {
    asm volatile("ldmatrix.sync.aligned.m8n8.x4.shared.b16 {%0,%1,%2,%3}, [%4];"
                 : "=r"(a[0]), "=r"(a[1]), "=r"(a[2]), "=r"(a[3])
                 : "r"(saddr));
}
__device__ __forceinline__ void mma16816(float* c, const unsigned* a, const unsigned* b) {
    asm volatile("mma.sync.aligned.m16n8k16.row.col.f32.f16.f16.f32 "
                 "{%0,%1,%2,%3}, {%4,%5,%6,%7}, {%8,%9}, {%0,%1,%2,%3};"
                 : "+f"(c[0]), "+f"(c[1]), "+f"(c[2]), "+f"(c[3])
                 : "r"(a[0]), "r"(a[1]), "r"(a[2]), "r"(a[3]),
                   "r"(b[0]), "r"(b[1]));
}

// ---------------------------------------------------------------------------
// Kernel 1: edge scatter — R13 instruction schedule untouched (80.7us).
// One EXTRA block (blockIdx == EDGE_BLOCKS) builds the mix kernel's B
// fragments concurrently with the scatter, so the mix prologue is free.
// ---------------------------------------------------------------------------
__global__ void __launch_bounds__(256)
edge_scatter_kernel(const float4* __restrict__ xe4,   // [E*3*8]
                    const float4* __restrict__ W4,    // [E*8]
                    const int*    __restrict__ src,
                    const int*    __restrict__ dst,
                    const float*  __restrict__ M1,
                    const float*  __restrict__ M2) {
    if (blockIdx.x == EDGE_BLOCKS) {
        // ---- B-fragment build (runs once, hidden under the scatter) ----
        int tid = threadIdx.x;
        if (tid < 128) {
            int warp = tid >> 5, lane = tid & 31;
            int q = lane & 3, g = lane >> 2;
            int n = warp * 8 + g;
            unsigned hi[8], lo[8];
#pragma unroll
            for (int ks = 0; ks < 2; ks++) {
#pragma unroll
                for (int r = 0; r < 2; r++) {
                    int k = ks * 16 + q * 2 + r * 8;
                    float m1a = M1[k * 32 + n],       m2a = M2[k * 32 + n];
                    float m1b = M1[(k + 1) * 32 + n], m2b = M2[(k + 1) * 32 + n];
                    float maa = 0.5f * (m1a + m2a), mab = 0.5f * (m1b + m2b);
                    float mba = 0.5f * (m2a - m1a), mbb = 0.5f * (m2b - m1b);

                    __half ha = __float2half_rn(maa), hb = __float2half_rn(mab);
                    hi[0 * 4 + ks * 2 + r] = pack_hh(ha, hb);
                    lo[0 * 4 + ks * 2 + r] = pack_hh(__float2half_rn(maa - __half2float(ha)),
                                                     __float2half_rn(mab - __half2float(hb)));
                    ha = __float2half_rn(mba); hb = __float2half_rn(mbb);
                    hi[1 * 4 + ks * 2 + r] = pack_hh(ha, hb);
                    lo[1 * 4 + ks * 2 + r] = pack_hh(__float2half_rn(mba - __half2float(ha)),
                                                     __float2half_rn(mbb - __half2float(hb)));
                }
            }
#pragma unroll
            for (int i = 0; i < 8; i++) {
                g_bfrag[tid * 16 + i]     = hi[i];
                g_bfrag[tid * 16 + 8 + i] = lo[i];
            }
        }
        return;
    }

    int gid = blockIdx.x * blockDim.x + threadIdx.x;
    int e   = gid >> 2;
    int sub = gid & 3;
    if (e >= N_EDGES) return;

    const float4* Wp = W4 + e * 8 + sub * 2;
    float4 w0 = ldcs_f4(&Wp[0]);
    float4 w1 = ldcs_f4(&Wp[1]);

    int d = __ldcs(&dst[e]);
    int s = __ldcs(&src[e]);

    char* p1 = reinterpret_cast<char*>(g_xn1) + (size_t)d * (ROW * 2) + sub * 16;
    char* p2 = reinterpret_cast<char*>(g_xn2) + (size_t)s * (ROW * 2) + sub * 16;

#pragma unroll
    for (int m = 0; m < MID; m++) {
        const float4* xp = xe4 + (e * MID + m) * 8 + sub * 2;
        float4 x0 = ldcs_f4(&xp[0]);
        float4 x1 = ldcs_f4(&xp[1]);

        unsigned h0 = pack_h2(w0.x * x0.x, w0.y * x0.y);
        unsigned h1 = pack_h2(w0.z * x0.z, w0.w * x0.w);
        unsigned h2 = pack_h2(w1.x * x1.x, w1.y * x1.y);
        unsigned h3 = pack_h2(w1.z * x1.z, w1.w * x1.w);

        red_add_v4_f16x2(p1 + m * (NVEC * 2), h0, h1, h2, h3);
        red_add_v4_f16x2(p2 + m * (NVEC * 2), h0, h1, h2, h3);
    }
}

// ---------------------------------------------------------------------------
// Kernel 2: tensor-core mix + zero-restore — exact R13 loop structure
// (1184 blocks, double-buffered cp.async), with the B-fragment prologue
// replaced by 4 x LDG.128 of the precomputed table (L2-hot broadcast).
// ---------------------------------------------------------------------------
__global__ void __launch_bounds__(128)
node_mix_mma_kernel(float* __restrict__ out) {
    __shared__ __align__(128) char sbuf[2][2][16 * SMEM_ROW_B];

    const int tid  = threadIdx.x;
    const int warp = tid >> 5;
    const int lane = tid & 31;
    const int q = lane & 3;
    const int g = lane >> 2;
    const int n0 = warp * 8;

    // ---- load precomputed B fragments: 16 words = 4 uint4 ----
    unsigned bh[2][2][2], bl[2][2][2];
    {
        const uint4* bp = reinterpret_cast<const uint4*>(&g_bfrag[tid * 16]);
        uint4 v0 = __ldg(&bp[0]);
        uint4 v1 = __ldg(&bp[1]);
        uint4 v2 = __ldg(&bp[2]);
        uint4 v3 = __ldg(&bp[3]);
        bh[0][0][0] = v0.x; bh[0][0][1] = v0.y; bh[0][1][0] = v0.z; bh[0][1][1] = v0.w;
        bh[1][0][0] = v1.x; bh[1][0][1] = v1.y; bh[1][1][0] = v1.z; bh[1][1][1] = v1.w;
        bl[0][0][0] = v2.x; bl[0][0][1] = v2.y; bl[0][1][0] = v2.z; bl[0][1][1] = v2.w;
        bl[1][0][0] = v3.x; bl[1][0][1] = v3.y; bl[1][1][0] = v3.z; bl[1][1][1] = v3.w;
    }

    const int arr    = tid >> 6;       // 0 -> xn1, 1 -> xn2
    const int idx    = tid & 63;
    const int crow   = idx >> 2;       // 0..15
    const int cchunk = idx & 3;        // 16B chunks of 64B row
    const char* gsrc = arr ? (const char*)g_xn2 : (const char*)g_xn1;
    char*       gdst = arr ? (char*)g_xn2 : (char*)g_xn1;

    int tile = blockIdx.x;
    int buf  = 0;

    if (tile < RTILES) {
        unsigned d = smem_u32(&sbuf[0][arr][crow * SMEM_ROW_B + cchunk * 16]);
        cpasync16(d, gsrc + (size_t)(tile * 16 + crow) * 64 + cchunk * 16);
    }
    asm volatile("cp.async.commit_group;" ::: "memory");

    for (; tile < RTILES; tile += MIX_BLOCKS) {
        int next = tile + MIX_BLOCKS;
        if (next < RTILES) {
            unsigned d = smem_u32(&sbuf[buf ^ 1][arr][crow * SMEM_ROW_B + cchunk * 16]);
            cpasync16(d, gsrc + (size_t)(next * 16 + crow) * 64 + cchunk * 16);
            asm volatile("cp.async.commit_group;" ::: "memory");
            asm volatile("cp.async.wait_group 1;" ::: "memory");
        } else {
            asm volatile("cp.async.wait_group 0;" ::: "memory");
        }
        __syncthreads();

        unsigned a1[2][4], a2[2][4];
        unsigned base1 = smem_u32(&sbuf[buf][0][0]) + (lane & 15) * SMEM_ROW_B + (lane >> 4) * 16;
        unsigned base2 = smem_u32(&sbuf[buf][1][0]) + (lane & 15) * SMEM_ROW_B + (lane >> 4) * 16;
        ldsm4(a1[0], base1);  ldsm4(a1[1], base1 + 32);
        ldsm4(a2[0], base2);  ldsm4(a2[1], base2 + 32);

        float c[4] = {0.f, 0.f, 0.f, 0.f};
#pragma unroll
        for (int ks = 0; ks < 2; ks++) {
            mma16816(c, a1[ks], bh[0][ks]);
            mma16816(c, a1[ks], bl[0][ks]);
            mma16816(c, a2[ks], bh[1][ks]);
            mma16816(c, a2[ks], bl[1][ks]);
        }

        int r0 = tile * 16 + g;
        *reinterpret_cast<float2*>(out + (size_t)r0 * 32 + n0 + q * 2)       = make_float2(c[0], c[1]);
        *reinterpret_cast<float2*>(out + (size_t)(r0 + 8) * 32 + n0 + q * 2) = make_float2(c[2], c[3]);

        // zero-restore this tile (reads ordered before stores by wait+barrier)
        const uint4 z = make_uint4(0u, 0u, 0u, 0u);
        *reinterpret_cast<uint4*>(gdst + (size_t)(tile * 16 + crow) * 64 + cchunk * 16) = z;

        buf ^= 1;
        __syncthreads();
    }
}

// ---------------------------------------------------------------------------
// Launch.  Inputs (metadata order): xe, W, M1, M2, xe_src, xe_dst, n_nodes
// ---------------------------------------------------------------------------
extern "C" void kernel_launch(void* const* d_in, const int* in_sizes, int n_in,
                              void* d_out, int out_size) {
    const float4* xe4 = (const float4*)d_in[0];
    const float4* W4  = (const float4*)d_in[1];
    const float*  M1  = (const float*)d_in[2];
    const float*  M2  = (const float*)d_in[3];
    const int*    src = (const int*)d_in[4];
    const int*    dst = (const int*)d_in[5];
    float* out = (float*)d_out;

    // 1) edge scatter (+1 block that builds B fragments concurrently)
    edge_scatter_kernel<<<EDGE_BLOCKS + 1, 256>>>(xe4, W4, src, dst, M1, M2);

    // 2) tensor-core mix + zero-restore (R13 config, prologue-free)
    node_mix_mma_kernel<<<MIX_BLOCKS, 128>>>(out);
}